// round 9
// baseline (speedup 1.0000x reference)
#include <cuda_runtime.h>
#include <cuda_fp16.h>
#include <cstdint>
#include <math.h>

// ================= problem constants =================
#define CIN_     64
#define HIN      56
#define HOUT     54
#define PIX_B    (HOUT * HOUT)              // 2916
#define BATCH    8
#define NPIX_TOT (BATCH * CIN_ * HIN * HIN) // 1605632
#define NROWS    (BATCH * PIX_B)            // 23328
#define COUT_    128
#define NIF      576                         // (c,kk) pairs
#define KSPL     4608                        // spline K: 576 * 8 f
#define KTOT     5184                        // + 576 silu
#define KC       64                          // K per stage
#define NSTG     (KTOT / KC)                 // 81 (72 spline + 9 silu)
#define NSPL_STG 72
#define MTILE    96
#define CTAS     (NROWS / MTILE)             // 243 exact
#define THREADS  320                         // 8 consumer warps + 2 producer warps

// smem geometry (halves)
#define SAK      72                          // A [m][k] row stride (9*16B, conflict-free)
#define SBH      72                          // B [n][k] row stride
#define A_STAGE_BYTES (MTILE * SAK * 2)      // 13824
#define B_STAGE_BYTES (COUT_ * SBH * 2)      // 18432
#define STAGE_BYTES   (A_STAGE_BYTES + B_STAGE_BYTES)  // 32256
#define NBUF     4
#define DYN_SMEM (NBUF * STAGE_BYTES + 256)  // 129280
#define SO       132                         // epilogue sout stride (floats)

// ================= device scratch (static; no allocs) =================
__device__ uint4  g_Fs[NPIX_TOT];            // 8 packed spline halves per pixel (16B)
__device__ __half g_Fsilu[NPIX_TOT];         // silu plane (source for pack)
__device__ __half g_As[NROWS * NIF];         // prepacked silu im2col block [n][i], 26.9MB
__device__ __half g_W2h[COUT_ * KTOT];       // weights [o][k]: k<4608 spline (c,kk,f), then silu
__device__ int    g_kmap2[NIF];              // (c*9+kk) -> c*3136 + ky*56 + kx

// ================= helpers =================
__device__ __forceinline__ uint32_t smem_u32(const void* p) {
    uint32_t a;
    asm("{ .reg .u64 t; cvta.to.shared.u64 t, %1; cvt.u32.u64 %0, t; }" : "=r"(a) : "l"(p));
    return a;
}
#define CP16(dst, src) asm volatile("cp.async.cg.shared.global [%0], [%1], 16;" :: "r"(dst), "l"(src) : "memory")
#define CPARRIVE(a)    asm volatile("cp.async.mbarrier.arrive.noinc.shared.b64 [%0];" :: "r"(a) : "memory")

#define MBAR_INIT(a, n)  asm volatile("mbarrier.init.shared.b64 [%0], %1;" :: "r"(a), "r"((uint32_t)(n)) : "memory")
#define MBAR_ARRIVE(a)   asm volatile("mbarrier.arrive.shared.b64 _, [%0];" :: "r"(a) : "memory")
#define MBAR_WAIT(a, ph) do { \
    uint32_t _m = (a), _p = (ph), _d; \
    asm volatile("{ .reg .pred p; mbarrier.try_wait.parity.acquire.cta.shared::cta.b64 p, [%1], %2; selp.b32 %0,1,0,p; }" \
        : "=r"(_d) : "r"(_m), "r"(_p) : "memory"); \
    if (!_d) { \
        asm volatile("{ .reg .pred P1; WL_%=: mbarrier.try_wait.parity.acquire.cta.shared::cta.b64 P1, [%0], %1, 0x989680; @P1 bra.uni WD_%=; bra.uni WL_%=; WD_%=: }" \
            :: "r"(_m), "r"(_p) : "memory"); \
    } } while (0)

__device__ __forceinline__ void ldsm4(uint32_t* r, uint32_t a) {
    asm volatile("ldmatrix.sync.aligned.m8n8.x4.shared.b16 {%0,%1,%2,%3}, [%4];"
        : "=r"(r[0]), "=r"(r[1]), "=r"(r[2]), "=r"(r[3]) : "r"(a));
}
__device__ __forceinline__ void mma16(float* c, const uint32_t* a, const uint32_t* b) {
    asm volatile("mma.sync.aligned.m16n8k16.row.col.f32.f16.f16.f32 "
        "{%0,%1,%2,%3}, {%4,%5,%6,%7}, {%8,%9}, {%0,%1,%2,%3};"
        : "+f"(c[0]), "+f"(c[1]), "+f"(c[2]), "+f"(c[3])
        : "r"(a[0]), "r"(a[1]), "r"(a[2]), "r"(a[3]), "r"(b[0]), "r"(b[1]));
}

// ================= stage 1: per-pixel features =================
__global__ __launch_bounds__(256) void kan_feat(const float* __restrict__ x) {
    int i = (blockIdx.x * blockDim.x + threadIdx.x) * 2;
    if (i >= NPIX_TOT) return;
    float2 vv = *(const float2*)(x + i);
    __half2 sil;
    uint4 spl[2];
#pragma unroll
    for (int p = 0; p < 2; ++p) {
        float v = p ? vv.y : vv.x;
        float s = v / (1.0f + expf(-v));
        float un = (v + 2.2f) * 2.5f;
        float sf = floorf(un);
        int   si = (int)sf;
        float u  = un - sf;
        float u2 = u * u, u3 = u2 * u;
        const float c6 = 1.0f / 6.0f;
        float pc[4];
        pc[0] = u3 * c6;
        pc[1] = (1.0f + 3.0f*u + 3.0f*u2 - 3.0f*u3) * c6;
        pc[2] = (4.0f - 6.0f*u2 + 3.0f*u3) * c6;
        pc[3] = (1.0f - 3.0f*u + 3.0f*u2 - u3) * c6;
        bool inr = (si >= 0) && (si <= 10);
        ((__half*)&sil)[p] = __float2half_rn(s);
        __half* sp = (__half*)&spl[p];
#pragma unroll
        for (int f = 0; f < 8; ++f) {
            int r = si - f;
            float b = (inr && r >= 0 && r <= 3) ? pc[r] : 0.0f;
            sp[f] = __float2half_rn(b);
        }
    }
    *(__half2*)(g_Fsilu + i) = sil;
    g_Fs[i]     = spl[0];
    g_Fs[i + 1] = spl[1];
}

// ================= stage 1b: pack silu im2col block [n][i] =================
// thread handles 8 consecutive i for one n -> one uint4 store (16B aligned).
__global__ __launch_bounds__(256) void kan_silu_pack() {
    int idx = blockIdx.x * blockDim.x + threadIdx.x;   // over NROWS * 72
    if (idx >= NROWS * (NIF / 8)) return;
    int n  = idx / (NIF / 8);
    int i0 = (idx - n * (NIF / 8)) * 8;
    int b   = n / PIX_B;
    int rem = n - b * PIX_B;
    int y   = rem / HOUT;
    int xx  = rem - y * HOUT;
    int roff = b * (CIN_ * HIN * HIN) + y * HIN + xx;
    __half v[8];
#pragma unroll
    for (int j = 0; j < 8; ++j)
        v[j] = g_Fsilu[g_kmap2[i0 + j] + roff];
    *(uint4*)(g_As + n * NIF + i0) = *(uint4*)v;
}

// ================= stage 2: weights + tap map =================
__global__ __launch_bounds__(256) void kan_wprep(const float* __restrict__ bw,
                                                 const float* __restrict__ sw,
                                                 const float* __restrict__ sc) {
    int idx = blockIdx.x * blockDim.x + threadIdx.x;
    if (idx < NIF) {
        int c  = idx / 9;
        int kk = idx - c * 9;
        int ky = kk / 3;
        int kx = kk - ky * 3;
        g_kmap2[idx] = c * (HIN * HIN) + ky * HIN + kx;
    }
    if (idx >= COUT_ * NIF) return;
    int o = idx & (COUT_ - 1);
    int i = idx >> 7;                        // 0..575 (= c*9+kk)
    float scale = sc[o * NIF + i];
    __half* dst = g_W2h + o * KTOT + i * 8;  // spline block: k = i*8 + f
#pragma unroll
    for (int g = 0; g < 8; ++g)
        dst[g] = __float2half_rn(sw[(o * NIF + i) * 8 + g] * scale);
    g_W2h[o * KTOT + KSPL + i] = __float2half_rn(bw[o * NIF + i]);   // silu block
}

// ================= stage 3: warp-specialized fp16 mma GEMM =================
// Warps 0-7: consumers (96x128 as 2m x 4n warps of 48x32), single fragment path.
// Warps 8-9: producers — 16B cp.async only; completion -> full[b] mbarrier.
__global__ __launch_bounds__(THREADS, 1) void kan_mma(float* __restrict__ out) {
    extern __shared__ char dsm_raw[];
    __shared__ int sh_roff[MTILE];
    __shared__ int sh_ooff[MTILE];
    __shared__ alignas(8) unsigned long long sh_mbar[2 * NBUF];  // full[0..3], empty[0..3]

    const uint32_t sb0 = smem_u32(dsm_raw);
    const uint32_t smb = (sb0 + 255) & ~255u;
    char* const dsm = dsm_raw + (smb - sb0);

    const int tid  = threadIdx.x;
    const int wid  = tid >> 5;
    const int lane = tid & 31;
    const int base_n = blockIdx.x * MTILE;

    const uint32_t mb_full  = smem_u32(&sh_mbar[0]);
    const uint32_t mb_empty = smem_u32(&sh_mbar[NBUF]);

    if (tid < MTILE) {
        int n   = base_n + tid;
        int b   = n / PIX_B;
        int rem = n - b * PIX_B;
        int y   = rem / HOUT;
        int xx  = rem - y * HOUT;
        sh_roff[tid] = b * (CIN_ * HIN * HIN) + y * HIN + xx;
        sh_ooff[tid] = b * (COUT_ * PIX_B) + rem;
    }
    if (tid == 0) {
#pragma unroll
        for (int b = 0; b < NBUF; ++b) {
            MBAR_INIT(mb_full  + b * 8, 64);   // cp.async completion from 64 producer threads
            MBAR_INIT(mb_empty + b * 8, 256);  // 256 consumer threads
        }
    }
    __syncthreads();

    if (wid >= 8) {
        // ================== PRODUCERS (warps 8-9, 64 threads) ==================
        const int p  = tid - 256;
        const int hi = p >> 3;               // 0..7
        const int lo = p & 7;                // 0..7
        for (int s = 0; s < NSTG; ++s) {
            const int buf = s & (NBUF - 1);
            MBAR_WAIT(mb_empty + buf * 8, ((s >> 2) & 1) ^ 1);
            const uint32_t Ab = smb + buf * STAGE_BYTES;
            const uint32_t Bb = Ab + A_STAGE_BYTES;
            if (s < NSPL_STG) {
                // A: 96 m x 8 f-groups of 16B. g=hi fixed, m=lo+8t.
                const int km = __ldg(g_kmap2 + s * 8 + hi);
#pragma unroll
                for (int t = 0; t < 12; ++t) {
                    int m = lo + 8 * t;
                    CP16(Ab + (uint32_t)(m * SAK + hi * 8) * 2,
                         (const char*)(g_Fs + km + sh_roff[m]));
                }
            } else {
                // A silu: 96 m x 8 chunks of 16B from prepacked g_As rows.
                const int k0 = (s - NSPL_STG) * KC;   // 0..512
#pragma unroll
                for (int t = 0; t < 12; ++t) {
                    int m = lo + 8 * t;
                    CP16(Ab + (uint32_t)(m * SAK + hi * 8) * 2,
                         (const char*)(g_As + (base_n + m) * NIF + k0 + hi * 8));
                }
            }
            // B: 128 n x 8 chunks of 16B. c=lo, n=hi+8t.
            {
                const __half* wb = g_W2h + s * KC + lo * 8;
#pragma unroll
                for (int t = 0; t < 16; ++t) {
                    int n = hi + 8 * t;
                    CP16(Bb + (uint32_t)(n * SBH + lo * 8) * 2, wb + n * KTOT);
                }
            }
            CPARRIVE(mb_full + buf * 8);
        }
        __syncthreads();   // match consumer epilogue barrier 1
        __syncthreads();   // match consumer epilogue barrier 2
        return;
    }

    // ================== CONSUMERS (warps 0-7) ==================
    const int wm = wid & 1;
    const int wn = wid >> 1;
    const uint32_t a_lane = (uint32_t)(((lane & 7) + (((lane >> 3) & 1) << 3)) * SAK
                                       + ((lane >> 4) << 3)) * 2;
    const uint32_t b_lane = (uint32_t)(((lane & 7) + ((lane >> 4) << 3)) * SBH
                                       + (((lane >> 3) & 1) << 3)) * 2;

    float acc[3][4][4];
#pragma unroll
    for (int mt = 0; mt < 3; ++mt)
#pragma unroll
        for (int nt = 0; nt < 4; ++nt)
#pragma unroll
            for (int e = 0; e < 4; ++e) acc[mt][nt][e] = 0.0f;

    for (int s = 0; s < NSTG; ++s) {
        const int buf = s & (NBUF - 1);
        MBAR_WAIT(mb_full + buf * 8, (s >> 2) & 1);
        const uint32_t Ab = smb + buf * STAGE_BYTES;
        const uint32_t Bb = Ab + A_STAGE_BYTES;
#pragma unroll
        for (int ks = 0; ks < 4; ++ks) {
            const int k0 = ks * 16;
            uint32_t a[3][4], b[2][4];
#pragma unroll
            for (int mt = 0; mt < 3; ++mt)
                ldsm4(a[mt], Ab + a_lane
                      + (uint32_t)((wm * 48 + mt * 16) * SAK + k0) * 2);
#pragma unroll
            for (int q = 0; q < 2; ++q)
                ldsm4(b[q], Bb + b_lane
                      + (uint32_t)((wn * 32 + q * 16) * SBH + k0) * 2);
#pragma unroll
            for (int mt = 0; mt < 3; ++mt)
#pragma unroll
                for (int nt = 0; nt < 4; ++nt)
                    mma16(acc[mt][nt], a[mt], &b[nt >> 1][(nt & 1) * 2]);
        }
        MBAR_ARRIVE(mb_empty + buf * 8);
    }

    __syncthreads();   // all buffers consumed -> reuse as sout

    // epilogue: regs -> smem transpose -> coalesced strided stores
    float* sout = (float*)dsm;
    const int g  = lane >> 2;
    const int t2 = (lane & 3) * 2;
#pragma unroll
    for (int mt = 0; mt < 3; ++mt) {
        int r = wm * 48 + mt * 16 + g;
#pragma unroll
        for (int nt = 0; nt < 4; ++nt) {
            int cc = wn * 32 + nt * 8 + t2;
            sout[r * SO + cc]           = acc[mt][nt][0];
            sout[r * SO + cc + 1]       = acc[mt][nt][1];
            sout[(r + 8) * SO + cc]     = acc[mt][nt][2];
            sout[(r + 8) * SO + cc + 1] = acc[mt][nt][3];
        }
    }
    __syncthreads();
#pragma unroll
    for (int o = wid; o < COUT_; o += 8) {
#pragma unroll
        for (int rg = 0; rg < 3; ++rg) {
            int r = rg * 32 + lane;
            out[sh_ooff[r] + o * PIX_B] = sout[r * SO + o];
        }
    }
}

// ================= launch =================
extern "C" void kernel_launch(void* const* d_in, const int* in_sizes, int n_in,
                              void* d_out, int out_size) {
    const float* x  = (const float*)d_in[0];   // (8,64,56,56)
    const float* bw = (const float*)d_in[1];   // (128,576)
    const float* sw = (const float*)d_in[2];   // (128,576,8)
    const float* sc = (const float*)d_in[3];   // (128,576)
    float* out = (float*)d_out;                // (8,128,54,54)
    (void)in_sizes; (void)n_in; (void)out_size;

    cudaFuncSetAttribute(kan_mma, cudaFuncAttributeMaxDynamicSharedMemorySize, DYN_SMEM);

    kan_wprep<<<(COUT_ * NIF + 255) / 256, 256>>>(bw, sw, sc);   // builds g_kmap2 first
    kan_feat<<<(NPIX_TOT / 2 + 255) / 256, 256>>>(x);
    kan_silu_pack<<<(NROWS * (NIF / 8) + 255) / 256, 256>>>();
    kan_mma<<<CTAS, THREADS, DYN_SMEM>>>(out);
}

// round 10
// speedup vs baseline: 1.1534x; 1.1534x over previous
#include <cuda_runtime.h>
#include <cuda_fp16.h>
#include <cstdint>
#include <math.h>

// ================= problem constants =================
#define CIN_     64
#define HIN      56
#define HOUT     54
#define PIX_B    (HOUT * HOUT)              // 2916
#define BATCH    8
#define NPIX_TOT (BATCH * CIN_ * HIN * HIN) // 1605632
#define NROWS    (BATCH * PIX_B)            // 23328
#define COUT_    128
#define NIF      576                         // (c,kk) pairs
#define KSPL     4608                        // spline K: 576 * 8 f
#define KTOT     5184                        // + 576 silu
#define KC       64                          // K per stage
#define NSTG     (KTOT / KC)                 // 81 (72 spline + 9 silu)
#define NSPL_STG 72
#define MTILE    96
#define CTAS     (NROWS / MTILE)             // 243 exact
#define THREADS  320                         // 8 consumer warps + 2 producer warps

// smem geometry (halves)
#define SAK      72                          // A [m][k] row stride (9*16B, conflict-free)
#define SBH      72                          // B [n][k] row stride
#define A_STAGE_BYTES (MTILE * SAK * 2)      // 13824
#define B_STAGE_BYTES (COUT_ * SBH * 2)      // 18432
#define STAGE_BYTES   (A_STAGE_BYTES + B_STAGE_BYTES)  // 32256
#define NBUF     3                           // 3-deep ring -> 2 CTAs/SM fit
#define DYN_SMEM (NBUF * STAGE_BYTES + 256)  // 97024
#define SO       132                         // epilogue sout stride (floats)

// ================= device scratch (static; no allocs) =================
__device__ uint4  g_Fs[NPIX_TOT];            // 8 packed spline halves per pixel (16B)
__device__ __half g_Fsilu[NPIX_TOT];         // silu plane (source for pack)
__device__ __half g_As[NROWS * NIF];         // prepacked silu im2col block [n][i], 26.9MB
__device__ __half g_W2h[COUT_ * KTOT];       // weights [o][k]: k<4608 spline (c,kk,f), then silu
__device__ int    g_kmap2[NIF];              // (c*9+kk) -> c*3136 + ky*56 + kx

// ================= helpers =================
__device__ __forceinline__ uint32_t smem_u32(const void* p) {
    uint32_t a;
    asm("{ .reg .u64 t; cvta.to.shared.u64 t, %1; cvt.u32.u64 %0, t; }" : "=r"(a) : "l"(p));
    return a;
}
#define CP16(dst, src) asm volatile("cp.async.cg.shared.global [%0], [%1], 16;" :: "r"(dst), "l"(src) : "memory")
#define CPARRIVE(a)    asm volatile("cp.async.mbarrier.arrive.noinc.shared.b64 [%0];" :: "r"(a) : "memory")

#define MBAR_INIT(a, n)  asm volatile("mbarrier.init.shared.b64 [%0], %1;" :: "r"(a), "r"((uint32_t)(n)) : "memory")
#define MBAR_ARRIVE(a)   asm volatile("mbarrier.arrive.shared.b64 _, [%0];" :: "r"(a) : "memory")
#define MBAR_WAIT(a, ph) do { \
    uint32_t _m = (a), _p = (ph), _d; \
    asm volatile("{ .reg .pred p; mbarrier.try_wait.parity.acquire.cta.shared::cta.b64 p, [%1], %2; selp.b32 %0,1,0,p; }" \
        : "=r"(_d) : "r"(_m), "r"(_p) : "memory"); \
    if (!_d) { \
        asm volatile("{ .reg .pred P1; WL_%=: mbarrier.try_wait.parity.acquire.cta.shared::cta.b64 P1, [%0], %1, 0x989680; @P1 bra.uni WD_%=; bra.uni WL_%=; WD_%=: }" \
            :: "r"(_m), "r"(_p) : "memory"); \
    } } while (0)

__device__ __forceinline__ void ldsm4(uint32_t* r, uint32_t a) {
    asm volatile("ldmatrix.sync.aligned.m8n8.x4.shared.b16 {%0,%1,%2,%3}, [%4];"
        : "=r"(r[0]), "=r"(r[1]), "=r"(r[2]), "=r"(r[3]) : "r"(a));
}
__device__ __forceinline__ void mma16(float* c, const uint32_t* a, const uint32_t* b) {
    asm volatile("mma.sync.aligned.m16n8k16.row.col.f32.f16.f16.f32 "
        "{%0,%1,%2,%3}, {%4,%5,%6,%7}, {%8,%9}, {%0,%1,%2,%3};"
        : "+f"(c[0]), "+f"(c[1]), "+f"(c[2]), "+f"(c[3])
        : "r"(a[0]), "r"(a[1]), "r"(a[2]), "r"(a[3]), "r"(b[0]), "r"(b[1]));
}

// ================= stage 1: per-pixel features =================
__global__ __launch_bounds__(256) void kan_feat(const float* __restrict__ x) {
    int i = (blockIdx.x * blockDim.x + threadIdx.x) * 2;
    if (i >= NPIX_TOT) return;
    float2 vv = *(const float2*)(x + i);
    __half2 sil;
    uint4 spl[2];
#pragma unroll
    for (int p = 0; p < 2; ++p) {
        float v = p ? vv.y : vv.x;
        float s = v / (1.0f + expf(-v));
        float un = (v + 2.2f) * 2.5f;
        float sf = floorf(un);
        int   si = (int)sf;
        float u  = un - sf;
        float u2 = u * u, u3 = u2 * u;
        const float c6 = 1.0f / 6.0f;
        float pc[4];
        pc[0] = u3 * c6;
        pc[1] = (1.0f + 3.0f*u + 3.0f*u2 - 3.0f*u3) * c6;
        pc[2] = (4.0f - 6.0f*u2 + 3.0f*u3) * c6;
        pc[3] = (1.0f - 3.0f*u + 3.0f*u2 - u3) * c6;
        bool inr = (si >= 0) && (si <= 10);
        ((__half*)&sil)[p] = __float2half_rn(s);
        __half* sp = (__half*)&spl[p];
#pragma unroll
        for (int f = 0; f < 8; ++f) {
            int r = si - f;
            float b = (inr && r >= 0 && r <= 3) ? pc[r] : 0.0f;
            sp[f] = __float2half_rn(b);
        }
    }
    *(__half2*)(g_Fsilu + i) = sil;
    g_Fs[i]     = spl[0];
    g_Fs[i + 1] = spl[1];
}

// ================= stage 1b: pack silu im2col block [n][i] =================
__global__ __launch_bounds__(256) void kan_silu_pack() {
    int idx = blockIdx.x * blockDim.x + threadIdx.x;   // over NROWS * 72
    if (idx >= NROWS * (NIF / 8)) return;
    int n  = idx / (NIF / 8);
    int i0 = (idx - n * (NIF / 8)) * 8;
    int b   = n / PIX_B;
    int rem = n - b * PIX_B;
    int y   = rem / HOUT;
    int xx  = rem - y * HOUT;
    int roff = b * (CIN_ * HIN * HIN) + y * HIN + xx;
    __half v[8];
#pragma unroll
    for (int j = 0; j < 8; ++j)
        v[j] = g_Fsilu[g_kmap2[i0 + j] + roff];
    *(uint4*)(g_As + n * NIF + i0) = *(uint4*)v;
}

// ================= stage 2: weights + tap map =================
__global__ __launch_bounds__(256) void kan_wprep(const float* __restrict__ bw,
                                                 const float* __restrict__ sw,
                                                 const float* __restrict__ sc) {
    int idx = blockIdx.x * blockDim.x + threadIdx.x;
    if (idx < NIF) {
        int c  = idx / 9;
        int kk = idx - c * 9;
        int ky = kk / 3;
        int kx = kk - ky * 3;
        g_kmap2[idx] = c * (HIN * HIN) + ky * HIN + kx;
    }
    if (idx >= COUT_ * NIF) return;
    int o = idx & (COUT_ - 1);
    int i = idx >> 7;                        // 0..575 (= c*9+kk)
    float scale = sc[o * NIF + i];
    __half* dst = g_W2h + o * KTOT + i * 8;  // spline block: k = i*8 + f
#pragma unroll
    for (int g = 0; g < 8; ++g)
        dst[g] = __float2half_rn(sw[(o * NIF + i) * 8 + g] * scale);
    g_W2h[o * KTOT + KSPL + i] = __float2half_rn(bw[o * NIF + i]);   // silu block
}

// ================= stage 3: warp-specialized fp16 mma GEMM, 2 CTAs/SM ==========
__global__ __launch_bounds__(THREADS, 2) void kan_mma(float* __restrict__ out) {
    extern __shared__ char dsm_raw[];
    __shared__ int sh_roff[MTILE];
    __shared__ int sh_ooff[MTILE];
    __shared__ alignas(8) unsigned long long sh_mbar[2 * NBUF];  // full[0..2], empty[0..2]

    const uint32_t sb0 = smem_u32(dsm_raw);
    const uint32_t smb = (sb0 + 255) & ~255u;
    char* const dsm = dsm_raw + (smb - sb0);

    const int tid  = threadIdx.x;
    const int wid  = tid >> 5;
    const int lane = tid & 31;
    const int base_n = blockIdx.x * MTILE;

    const uint32_t mb_full  = smem_u32(&sh_mbar[0]);
    const uint32_t mb_empty = smem_u32(&sh_mbar[NBUF]);

    if (tid < MTILE) {
        int n   = base_n + tid;
        int b   = n / PIX_B;
        int rem = n - b * PIX_B;
        int y   = rem / HOUT;
        int xx  = rem - y * HOUT;
        sh_roff[tid] = b * (CIN_ * HIN * HIN) + y * HIN + xx;
        sh_ooff[tid] = b * (COUT_ * PIX_B) + rem;
    }
    if (tid == 0) {
#pragma unroll
        for (int b = 0; b < NBUF; ++b) {
            MBAR_INIT(mb_full  + b * 8, 64);   // cp.async completion from 64 producer threads
            MBAR_INIT(mb_empty + b * 8, 256);  // 256 consumer threads
        }
    }
    __syncthreads();

    if (wid >= 8) {
        // ================== PRODUCERS (warps 8-9, 64 threads) ==================
        const int p  = tid - 256;
        const int hi = p >> 3;               // 0..7
        const int lo = p & 7;                // 0..7
        int buf = 0, ph = 1;                 // producer cursor: first empty-wait passes
        for (int s = 0; s < NSTG; ++s) {
            MBAR_WAIT(mb_empty + buf * 8, ph);
            const uint32_t Ab = smb + buf * STAGE_BYTES;
            const uint32_t Bb = Ab + A_STAGE_BYTES;
            if (s < NSPL_STG) {
                // A: 96 m x 8 f-groups of 16B. g=hi fixed, m=lo+8t.
                const int km = __ldg(g_kmap2 + s * 8 + hi);
#pragma unroll
                for (int t = 0; t < 12; ++t) {
                    int m = lo + 8 * t;
                    CP16(Ab + (uint32_t)(m * SAK + hi * 8) * 2,
                         (const char*)(g_Fs + km + sh_roff[m]));
                }
            } else {
                // A silu: 96 m x 8 chunks of 16B from prepacked g_As rows.
                const int k0 = (s - NSPL_STG) * KC;
#pragma unroll
                for (int t = 0; t < 12; ++t) {
                    int m = lo + 8 * t;
                    CP16(Ab + (uint32_t)(m * SAK + hi * 8) * 2,
                         (const char*)(g_As + (base_n + m) * NIF + k0 + hi * 8));
                }
            }
            // B: 128 n x 8 chunks of 16B. c=lo, n=hi+8t.
            {
                const __half* wb = g_W2h + s * KC + lo * 8;
#pragma unroll
                for (int t = 0; t < 16; ++t) {
                    int n = hi + 8 * t;
                    CP16(Bb + (uint32_t)(n * SBH + lo * 8) * 2, wb + n * KTOT);
                }
            }
            CPARRIVE(mb_full + buf * 8);
            if (++buf == NBUF) { buf = 0; ph ^= 1; }
        }
        __syncthreads();   // match consumer epilogue barrier 1
        __syncthreads();   // match consumer epilogue barrier 2
        return;
    }

    // ================== CONSUMERS (warps 0-7) ==================
    const int wm = wid & 1;
    const int wn = wid >> 1;
    const uint32_t a_lane = (uint32_t)(((lane & 7) + (((lane >> 3) & 1) << 3)) * SAK
                                       + ((lane >> 4) << 3)) * 2;
    const uint32_t b_lane = (uint32_t)(((lane & 7) + ((lane >> 4) << 3)) * SBH
                                       + (((lane >> 3) & 1) << 3)) * 2;

    float acc[3][4][4];
#pragma unroll
    for (int mt = 0; mt < 3; ++mt)
#pragma unroll
        for (int nt = 0; nt < 4; ++nt)
#pragma unroll
            for (int e = 0; e < 4; ++e) acc[mt][nt][e] = 0.0f;

    int buf = 0, ph = 0;                     // consumer cursor
    for (int s = 0; s < NSTG; ++s) {
        MBAR_WAIT(mb_full + buf * 8, ph);
        const uint32_t Ab = smb + buf * STAGE_BYTES;
        const uint32_t Bb = Ab + A_STAGE_BYTES;
#pragma unroll
        for (int ks = 0; ks < 4; ++ks) {
            const int k0 = ks * 16;
            uint32_t a[3][4], b[2][4];
#pragma unroll
            for (int mt = 0; mt < 3; ++mt)
                ldsm4(a[mt], Ab + a_lane
                      + (uint32_t)((wm * 48 + mt * 16) * SAK + k0) * 2);
#pragma unroll
            for (int q = 0; q < 2; ++q)
                ldsm4(b[q], Bb + b_lane
                      + (uint32_t)((wn * 32 + q * 16) * SBH + k0) * 2);
#pragma unroll
            for (int mt = 0; mt < 3; ++mt)
#pragma unroll
                for (int nt = 0; nt < 4; ++nt)
                    mma16(acc[mt][nt], a[mt], &b[nt >> 1][(nt & 1) * 2]);
        }
        MBAR_ARRIVE(mb_empty + buf * 8);
        if (++buf == NBUF) { buf = 0; ph ^= 1; }
    }

    __syncthreads();   // all buffers consumed -> reuse as sout

    // epilogue: regs -> smem transpose -> coalesced strided stores
    float* sout = (float*)dsm;
    const int g  = lane >> 2;
    const int t2 = (lane & 3) * 2;
#pragma unroll
    for (int mt = 0; mt < 3; ++mt) {
        int r = wm * 48 + mt * 16 + g;
#pragma unroll
        for (int nt = 0; nt < 4; ++nt) {
            int cc = wn * 32 + nt * 8 + t2;
            sout[r * SO + cc]           = acc[mt][nt][0];
            sout[r * SO + cc + 1]       = acc[mt][nt][1];
            sout[(r + 8) * SO + cc]     = acc[mt][nt][2];
            sout[(r + 8) * SO + cc + 1] = acc[mt][nt][3];
        }
    }
    __syncthreads();
#pragma unroll
    for (int o = wid; o < COUT_; o += 8) {
#pragma unroll
        for (int rg = 0; rg < 3; ++rg) {
            int r = rg * 32 + lane;
            out[sh_ooff[r] + o * PIX_B] = sout[r * SO + o];
        }
    }
}

// ================= launch =================
extern "C" void kernel_launch(void* const* d_in, const int* in_sizes, int n_in,
                              void* d_out, int out_size) {
    const float* x  = (const float*)d_in[0];   // (8,64,56,56)
    const float* bw = (const float*)d_in[1];   // (128,576)
    const float* sw = (const float*)d_in[2];   // (128,576,8)
    const float* sc = (const float*)d_in[3];   // (128,576)
    float* out = (float*)d_out;                // (8,128,54,54)
    (void)in_sizes; (void)n_in; (void)out_size;

    cudaFuncSetAttribute(kan_mma, cudaFuncAttributeMaxDynamicSharedMemorySize, DYN_SMEM);

    kan_wprep<<<(COUT_ * NIF + 255) / 256, 256>>>(bw, sw, sc);   // builds g_kmap2 first
    kan_feat<<<(NPIX_TOT / 2 + 255) / 256, 256>>>(x);
    kan_silu_pack<<<(NROWS * (NIF / 8) + 255) / 256, 256>>>();
    kan_mma<<<CTAS, THREADS, DYN_SMEM>>>(out);
}

// round 12
// speedup vs baseline: 1.2536x; 1.0868x over previous
#include <cuda_runtime.h>
#include <cuda_fp16.h>
#include <cstdint>
#include <math.h>

// ================= problem constants =================
#define CIN_     64
#define HIN      56
#define HOUT     54
#define PIX_B    (HOUT * HOUT)              // 2916
#define BATCH    8
#define NPIX_TOT (BATCH * CIN_ * HIN * HIN) // 1605632
#define NROWS    (BATCH * PIX_B)            // 23328
#define COUT_    128
#define NIF      576                         // (c,kk) pairs
#define KSPL     4608                        // spline K: 576 * 8 f
#define KTOT     5184                        // + 576 silu
#define KC       64                          // K per stage
#define NSTG     (KTOT / KC)                 // 81 (72 spline + 9 silu)
#define NSPL_STG 72
#define MTILE    96
#define CTAS     (NROWS / MTILE)             // 243 exact
#define THREADS  192                         // 4 consumer warps (48x64 each) + 2 producer warps

// smem geometry (halves)
#define SAK      72                          // A [m][k] row stride (9*16B, conflict-free)
#define SBH      72                          // B [n][k] row stride
#define A_STAGE_BYTES (MTILE * SAK * 2)      // 13824
#define B_STAGE_BYTES (COUT_ * SBH * 2)      // 18432
#define STAGE_BYTES   (A_STAGE_BYTES + B_STAGE_BYTES)  // 32256
#define NBUF     3                           // 2 CTAs/SM fit
#define DYN_SMEM (NBUF * STAGE_BYTES + 256)  // 97024
#define SO       132                         // epilogue sout stride (floats)

// ================= device scratch (static; no allocs) =================
__device__ uint4  g_Fs[NPIX_TOT];            // 8 packed spline halves per pixel (16B)
__device__ __half g_Fsilu[NPIX_TOT];         // silu plane (source for pack)
__device__ __half g_As[NROWS * NIF];         // prepacked silu im2col block [n][i], 26.9MB
__device__ __half g_W2h[COUT_ * KTOT];       // weights [o][k]: k<4608 spline (c,kk,f), then silu
__device__ int    g_kmap2[NIF];              // (c*9+kk) -> c*3136 + ky*56 + kx

// ================= helpers =================
__device__ __forceinline__ uint32_t smem_u32(const void* p) {
    uint32_t a;
    asm("{ .reg .u64 t; cvta.to.shared.u64 t, %1; cvt.u32.u64 %0, t; }" : "=r"(a) : "l"(p));
    return a;
}
#define CP16(dst, src) asm volatile("cp.async.cg.shared.global [%0], [%1], 16;" :: "r"(dst), "l"(src) : "memory")
#define CPARRIVE(a)    asm volatile("cp.async.mbarrier.arrive.noinc.shared.b64 [%0];" :: "r"(a) : "memory")

#define MBAR_INIT(a, n)  asm volatile("mbarrier.init.shared.b64 [%0], %1;" :: "r"(a), "r"((uint32_t)(n)) : "memory")
#define MBAR_ARRIVE(a)   asm volatile("mbarrier.arrive.shared.b64 _, [%0];" :: "r"(a) : "memory")
#define MBAR_WAIT(a, ph) do { \
    uint32_t _m = (a), _p = (ph), _d; \
    asm volatile("{ .reg .pred p; mbarrier.try_wait.parity.acquire.cta.shared::cta.b64 p, [%1], %2; selp.b32 %0,1,0,p; }" \
        : "=r"(_d) : "r"(_m), "r"(_p) : "memory"); \
    if (!_d) { \
        asm volatile("{ .reg .pred P1; WL_%=: mbarrier.try_wait.parity.acquire.cta.shared::cta.b64 P1, [%0], %1, 0x989680; @P1 bra.uni WD_%=; bra.uni WL_%=; WD_%=: }" \
            :: "r"(_m), "r"(_p) : "memory"); \
    } } while (0)

__device__ __forceinline__ void ldsm4(uint32_t* r, uint32_t a) {
    asm volatile("ldmatrix.sync.aligned.m8n8.x4.shared.b16 {%0,%1,%2,%3}, [%4];"
        : "=r"(r[0]), "=r"(r[1]), "=r"(r[2]), "=r"(r[3]) : "r"(a));
}
__device__ __forceinline__ void mma16(float* c, const uint32_t* a, const uint32_t* b) {
    asm volatile("mma.sync.aligned.m16n8k16.row.col.f32.f16.f16.f32 "
        "{%0,%1,%2,%3}, {%4,%5,%6,%7}, {%8,%9}, {%0,%1,%2,%3};"
        : "+f"(c[0]), "+f"(c[1]), "+f"(c[2]), "+f"(c[3])
        : "r"(a[0]), "r"(a[1]), "r"(a[2]), "r"(a[3]), "r"(b[0]), "r"(b[1]));
}

// ================= stage 1: per-pixel features =================
__global__ __launch_bounds__(256) void kan_feat(const float* __restrict__ x) {
    int i = (blockIdx.x * blockDim.x + threadIdx.x) * 2;
    if (i >= NPIX_TOT) return;
    float2 vv = *(const float2*)(x + i);
    __half2 sil;
    uint4 spl[2];
#pragma unroll
    for (int p = 0; p < 2; ++p) {
        float v = p ? vv.y : vv.x;
        float s = v / (1.0f + expf(-v));
        float un = (v + 2.2f) * 2.5f;
        float sf = floorf(un);
        int   si = (int)sf;
        float u  = un - sf;
        float u2 = u * u, u3 = u2 * u;
        const float c6 = 1.0f / 6.0f;
        float pc[4];
        pc[0] = u3 * c6;
        pc[1] = (1.0f + 3.0f*u + 3.0f*u2 - 3.0f*u3) * c6;
        pc[2] = (4.0f - 6.0f*u2 + 3.0f*u3) * c6;
        pc[3] = (1.0f - 3.0f*u + 3.0f*u2 - u3) * c6;
        bool inr = (si >= 0) && (si <= 10);
        ((__half*)&sil)[p] = __float2half_rn(s);
        __half* sp = (__half*)&spl[p];
#pragma unroll
        for (int f = 0; f < 8; ++f) {
            int r = si - f;
            float b = (inr && r >= 0 && r <= 3) ? pc[r] : 0.0f;
            sp[f] = __float2half_rn(b);
        }
    }
    *(__half2*)(g_Fsilu + i) = sil;
    g_Fs[i]     = spl[0];
    g_Fs[i + 1] = spl[1];
}

// ================= stage 1b: pack silu im2col block [n][i] =================
__global__ __launch_bounds__(256) void kan_silu_pack() {
    int idx = blockIdx.x * blockDim.x + threadIdx.x;   // over NROWS * 72
    if (idx >= NROWS * (NIF / 8)) return;
    int n  = idx / (NIF / 8);
    int i0 = (idx - n * (NIF / 8)) * 8;
    int b   = n / PIX_B;
    int rem = n - b * PIX_B;
    int y   = rem / HOUT;
    int xx  = rem - y * HOUT;
    int roff = b * (CIN_ * HIN * HIN) + y * HIN + xx;
    __half v[8];
#pragma unroll
    for (int j = 0; j < 8; ++j)
        v[j] = g_Fsilu[g_kmap2[i0 + j] + roff];
    *(uint4*)(g_As + n * NIF + i0) = *(uint4*)v;
}

// ================= stage 2: weights + tap map =================
__global__ __launch_bounds__(256) void kan_wprep(const float* __restrict__ bw,
                                                 const float* __restrict__ sw,
                                                 const float* __restrict__ sc) {
    int idx = blockIdx.x * blockDim.x + threadIdx.x;
    if (idx < NIF) {
        int c  = idx / 9;
        int kk = idx - c * 9;
        int ky = kk / 3;
        int kx = kk - ky * 3;
        g_kmap2[idx] = c * (HIN * HIN) + ky * HIN + kx;
    }
    if (idx >= COUT_ * NIF) return;
    int o = idx & (COUT_ - 1);
    int i = idx >> 7;                        // 0..575 (= c*9+kk)
    float scale = sc[o * NIF + i];
    __half* dst = g_W2h + o * KTOT + i * 8;  // spline block: k = i*8 + f
#pragma unroll
    for (int g = 0; g < 8; ++g)
        dst[g] = __float2half_rn(sw[(o * NIF + i) * 8 + g] * scale);
    g_W2h[o * KTOT + KSPL + i] = __float2half_rn(bw[o * NIF + i]);   // silu block
}

// ================= stage 3: warp-specialized fp16 mma GEMM =================
// 4 consumer warps (wid 0-3): warp tile 48x64, 2m x 2n grid -> A read 2x, B 2x
// (56KB crossbar/stage vs 80KB with the 2x4 grid). 2 producer warps (wid 4-5).
__global__ __launch_bounds__(THREADS, 2) void kan_mma(float* __restrict__ out) {
    extern __shared__ char dsm_raw[];
    __shared__ int sh_roff[MTILE];
    __shared__ int sh_ooff[MTILE];
    __shared__ alignas(8) unsigned long long sh_mbar[2 * NBUF];  // full[0..2], empty[0..2]

    const uint32_t sb0 = smem_u32(dsm_raw);
    const uint32_t smb = (sb0 + 255) & ~255u;
    char* const dsm = dsm_raw + (smb - sb0);

    const int tid  = threadIdx.x;
    const int wid  = tid >> 5;
    const int lane = tid & 31;
    const int base_n = blockIdx.x * MTILE;

    const uint32_t mb_full  = smem_u32(&sh_mbar[0]);
    const uint32_t mb_empty = smem_u32(&sh_mbar[NBUF]);

    if (tid < MTILE) {
        int n   = base_n + tid;
        int b   = n / PIX_B;
        int rem = n - b * PIX_B;
        int y   = rem / HOUT;
        int xx  = rem - y * HOUT;
        sh_roff[tid] = b * (CIN_ * HIN * HIN) + y * HIN + xx;
        sh_ooff[tid] = b * (COUT_ * PIX_B) + rem;
    }
    if (tid == 0) {
#pragma unroll
        for (int b = 0; b < NBUF; ++b) {
            MBAR_INIT(mb_full  + b * 8, 64);   // cp.async completion from 64 producer threads
            MBAR_INIT(mb_empty + b * 8, 128);  // 128 consumer threads
        }
    }
    __syncthreads();

    if (wid >= 4) {
        // ================== PRODUCERS (warps 4-5, 64 threads) ==================
        const int p  = tid - 128;
        const int hi = p >> 3;               // 0..7
        const int lo = p & 7;                // 0..7
        int buf = 0, ph = 1;                 // producer cursor: first empty-wait passes
        for (int s = 0; s < NSTG; ++s) {
            MBAR_WAIT(mb_empty + buf * 8, ph);
            const uint32_t Ab = smb + buf * STAGE_BYTES;
            const uint32_t Bb = Ab + A_STAGE_BYTES;
            if (s < NSPL_STG) {
                // A: 96 m x 8 f-groups of 16B. g=hi fixed, m=lo+8t.
                const int km = __ldg(g_kmap2 + s * 8 + hi);
#pragma unroll
                for (int t = 0; t < 12; ++t) {
                    int m = lo + 8 * t;
                    CP16(Ab + (uint32_t)(m * SAK + hi * 8) * 2,
                         (const char*)(g_Fs + km + sh_roff[m]));
                }
            } else {
                // A silu: 96 m x 8 chunks of 16B from prepacked g_As rows.
                const int k0 = (s - NSPL_STG) * KC;
#pragma unroll
                for (int t = 0; t < 12; ++t) {
                    int m = lo + 8 * t;
                    CP16(Ab + (uint32_t)(m * SAK + hi * 8) * 2,
                         (const char*)(g_As + (base_n + m) * NIF + k0 + hi * 8));
                }
            }
            // B: 128 n x 8 chunks of 16B. c=lo, n=hi+8t.
            {
                const __half* wb = g_W2h + s * KC + lo * 8;
#pragma unroll
                for (int t = 0; t < 16; ++t) {
                    int n = hi + 8 * t;
                    CP16(Bb + (uint32_t)(n * SBH + lo * 8) * 2, wb + n * KTOT);
                }
            }
            CPARRIVE(mb_full + buf * 8);
            if (++buf == NBUF) { buf = 0; ph ^= 1; }
        }
        __syncthreads();   // match consumer epilogue barrier 1
        __syncthreads();   // match consumer epilogue barrier 2
        return;
    }

    // ================== CONSUMERS (warps 0-3, 48x64 tiles) ==================
    const int wm = wid & 1;                  // rows wm*48
    const int wn = wid >> 1;                 // cols wn*64
    const uint32_t a_lane = (uint32_t)(((lane & 7) + (((lane >> 3) & 1) << 3)) * SAK
                                       + ((lane >> 4) << 3)) * 2;
    const uint32_t b_lane = (uint32_t)(((lane & 7) + ((lane >> 4) << 3)) * SBH
                                       + (((lane >> 3) & 1) << 3)) * 2;

    float acc[3][8][4];
#pragma unroll
    for (int mt = 0; mt < 3; ++mt)
#pragma unroll
        for (int nt = 0; nt < 8; ++nt)
#pragma unroll
            for (int e = 0; e < 4; ++e) acc[mt][nt][e] = 0.0f;

    int buf = 0, ph = 0;                     // consumer cursor
    for (int s = 0; s < NSTG; ++s) {
        MBAR_WAIT(mb_full + buf * 8, ph);
        const uint32_t Ab = smb + buf * STAGE_BYTES;
        const uint32_t Bb = Ab + A_STAGE_BYTES;
#pragma unroll
        for (int ks = 0; ks < 4; ++ks) {
            const int k0 = ks * 16;
            uint32_t a[3][4], b[4][4];
#pragma unroll
            for (int mt = 0; mt < 3; ++mt)
                ldsm4(a[mt], Ab + a_lane
                      + (uint32_t)((wm * 48 + mt * 16) * SAK + k0) * 2);
#pragma unroll
            for (int q = 0; q < 4; ++q)
                ldsm4(b[q], Bb + b_lane
                      + (uint32_t)((wn * 64 + q * 16) * SBH + k0) * 2);
#pragma unroll
            for (int mt = 0; mt < 3; ++mt)
#pragma unroll
                for (int nt = 0; nt < 8; ++nt)
                    mma16(acc[mt][nt], a[mt], &b[nt >> 1][(nt & 1) * 2]);
        }
        MBAR_ARRIVE(mb_empty + buf * 8);
        if (++buf == NBUF) { buf = 0; ph ^= 1; }
    }

    __syncthreads();   // all buffers consumed -> reuse as sout

    // epilogue: regs -> smem transpose -> coalesced strided stores
    float* sout = (float*)dsm;
    const int g  = lane >> 2;
    const int t2 = (lane & 3) * 2;
#pragma unroll
    for (int mt = 0; mt < 3; ++mt) {
        int r = wm * 48 + mt * 16 + g;
#pragma unroll
        for (int nt = 0; nt < 8; ++nt) {
            int cc = wn * 64 + nt * 8 + t2;
            sout[r * SO + cc]           = acc[mt][nt][0];
            sout[r * SO + cc + 1]       = acc[mt][nt][1];
            sout[(r + 8) * SO + cc]     = acc[mt][nt][2];
            sout[(r + 8) * SO + cc + 1] = acc[mt][nt][3];
        }
    }
    __syncthreads();
#pragma unroll
    for (int o = wid; o < COUT_; o += 4) {
#pragma unroll
        for (int rg = 0; rg < 3; ++rg) {
            int r = rg * 32 + lane;
            out[sh_ooff[r] + o * PIX_B] = sout[r * SO + o];
        }
    }
}

// ================= launch =================
extern "C" void kernel_launch(void* const* d_in, const int* in_sizes, int n_in,
                              void* d_out, int out_size) {
    const float* x  = (const float*)d_in[0];   // (8,64,56,56)
    const float* bw = (const float*)d_in[1];   // (128,576)
    const float* sw = (const float*)d_in[2];   // (128,576,8)
    const float* sc = (const float*)d_in[3];   // (128,576)
    float* out = (float*)d_out;                // (8,128,54,54)
    (void)in_sizes; (void)n_in; (void)out_size;

    cudaFuncSetAttribute(kan_mma, cudaFuncAttributeMaxDynamicSharedMemorySize, DYN_SMEM);

    kan_wprep<<<(COUT_ * NIF + 255) / 256, 256>>>(bw, sw, sc);   // builds g_kmap2 first
    kan_feat<<<(NPIX_TOT / 2 + 255) / 256, 256>>>(x);
    kan_silu_pack<<<(NROWS * (NIF / 8) + 255) / 256, 256>>>();
    kan_mma<<<CTAS, THREADS, DYN_SMEM>>>(out);
}

// round 15
// speedup vs baseline: 1.3686x; 1.0917x over previous
#include <cuda_runtime.h>
#include <cuda_fp16.h>
#include <cstdint>
#include <math.h>

// ================= problem constants =================
#define CIN_     64
#define HIN      56
#define HOUT     54
#define PIX_B    (HOUT * HOUT)              // 2916
#define BATCH    8
#define NPIX_TOT (BATCH * CIN_ * HIN * HIN) // 1605632
#define NROWS    (BATCH * PIX_B)            // 23328
#define COUT_    128
#define NIF      576                         // (c,kk) pairs
#define KSPL     4608                        // spline K: 576 * 8 f
#define KTOT     5184                        // + 576 silu
#define KC       64                          // K per stage
#define NSTG     (KTOT / KC)                 // 81 (72 spline + 9 silu)
#define NSPL_STG 72
#define MTILE    96
#define CTAS     (NROWS / MTILE)             // 243 exact
#define THREADS  192                         // 4 consumer warps (48x64 each) + 2 producer warps

// smem geometry (halves)
#define SAK      72                          // A [m][k] row stride (9*16B, conflict-free)
#define SBH      72                          // B [n][k] row stride
#define A_STAGE_BYTES (MTILE * SAK * 2)      // 13824
#define B_STAGE_BYTES (COUT_ * SBH * 2)      // 18432
#define STAGE_BYTES   (A_STAGE_BYTES + B_STAGE_BYTES)  // 32256
#define NBUF     3                           // 2 CTAs/SM fit
#define DYN_SMEM (NBUF * STAGE_BYTES + 256)  // 97024
#define SO       132                         // epilogue sout stride (floats)

// pack kernel tile
#define PK_STRIDE 584                        // halves; rows are 16B-aligned (584*2=1168=73*16)
#define PK_SMEM   (HOUT * PK_STRIDE * 2)     // 63072 bytes

// ================= device scratch (static; no allocs) =================
__device__ uint4  g_Fs[NPIX_TOT];            // 8 packed spline halves per pixel (16B)
__device__ __half g_Fsilu[NPIX_TOT];         // silu plane (source for pack)
__device__ __half g_As[NROWS * NIF];         // prepacked silu im2col block [n][i], 26.9MB
__device__ __half g_W2h[COUT_ * KTOT];       // weights [o][k]: k<4608 spline (c,kk,f), then silu
__device__ int    g_kmap2[NIF];              // (c*9+kk) -> c*3136 + ky*56 + kx

// ================= helpers =================
__device__ __forceinline__ uint32_t smem_u32(const void* p) {
    uint32_t a;
    asm("{ .reg .u64 t; cvta.to.shared.u64 t, %1; cvt.u32.u64 %0, t; }" : "=r"(a) : "l"(p));
    return a;
}
#define CP16(dst, src) asm volatile("cp.async.cg.shared.global [%0], [%1], 16;" :: "r"(dst), "l"(src) : "memory")
#define CPARRIVE(a)    asm volatile("cp.async.mbarrier.arrive.noinc.shared.b64 [%0];" :: "r"(a) : "memory")

#define MBAR_INIT(a, n)  asm volatile("mbarrier.init.shared.b64 [%0], %1;" :: "r"(a), "r"((uint32_t)(n)) : "memory")
#define MBAR_ARRIVE(a)   asm volatile("mbarrier.arrive.shared.b64 _, [%0];" :: "r"(a) : "memory")
#define MBAR_WAIT(a, ph) do { \
    uint32_t _m = (a), _p = (ph), _d; \
    asm volatile("{ .reg .pred p; mbarrier.try_wait.parity.acquire.cta.shared::cta.b64 p, [%1], %2; selp.b32 %0,1,0,p; }" \
        : "=r"(_d) : "r"(_m), "r"(_p) : "memory"); \
    if (!_d) { \
        asm volatile("{ .reg .pred P1; WL_%=: mbarrier.try_wait.parity.acquire.cta.shared::cta.b64 P1, [%0], %1, 0x989680; @P1 bra.uni WD_%=; bra.uni WL_%=; WD_%=: }" \
            :: "r"(_m), "r"(_p) : "memory"); \
    } } while (0)

__device__ __forceinline__ void ldsm4(uint32_t* r, uint32_t a) {
    asm volatile("ldmatrix.sync.aligned.m8n8.x4.shared.b16 {%0,%1,%2,%3}, [%4];"
        : "=r"(r[0]), "=r"(r[1]), "=r"(r[2]), "=r"(r[3]) : "r"(a));
}
__device__ __forceinline__ void mma16(float* c, const uint32_t* a, const uint32_t* b) {
    asm volatile("mma.sync.aligned.m16n8k16.row.col.f32.f16.f16.f32 "
        "{%0,%1,%2,%3}, {%4,%5,%6,%7}, {%8,%9}, {%0,%1,%2,%3};"
        : "+f"(c[0]), "+f"(c[1]), "+f"(c[2]), "+f"(c[3])
        : "r"(a[0]), "r"(a[1]), "r"(a[2]), "r"(a[3]), "r"(b[0]), "r"(b[1]));
}

// ================= stage 1: per-pixel features =================
__global__ __launch_bounds__(256) void kan_feat(const float* __restrict__ x) {
    int i = (blockIdx.x * blockDim.x + threadIdx.x) * 2;
    if (i >= NPIX_TOT) return;
    float2 vv = *(const float2*)(x + i);
    __half2 sil;
    uint4 spl[2];
#pragma unroll
    for (int p = 0; p < 2; ++p) {
        float v = p ? vv.y : vv.x;
        float s = v / (1.0f + expf(-v));
        float un = (v + 2.2f) * 2.5f;
        float sf = floorf(un);
        int   si = (int)sf;
        float u  = un - sf;
        float u2 = u * u, u3 = u2 * u;
        const float c6 = 1.0f / 6.0f;
        float pc[4];
        pc[0] = u3 * c6;
        pc[1] = (1.0f + 3.0f*u + 3.0f*u2 - 3.0f*u3) * c6;
        pc[2] = (4.0f - 6.0f*u2 + 3.0f*u3) * c6;
        pc[3] = (1.0f - 3.0f*u + 3.0f*u2 - u3) * c6;
        bool inr = (si >= 0) && (si <= 10);
        ((__half*)&sil)[p] = __float2half_rn(s);
        __half* sp = (__half*)&spl[p];
#pragma unroll
        for (int f = 0; f < 8; ++f) {
            int r = si - f;
            float b = (inr && r >= 0 && r <= 3) ? pc[r] : 0.0f;
            sp[f] = __float2half_rn(b);
        }
    }
    *(__half2*)(g_Fsilu + i) = sil;
    g_Fs[i]     = spl[0];
    g_Fs[i + 1] = spl[1];
}

// ================= stage 1b: pack silu im2col [n][i] via smem transpose ==========
// One block per output row (b, y): 54 output pixels. Phase 1: for each feature i,
// lanes sweep xx contiguously (coalesced 2B reads). Phase 2: uint4 row writes.
__global__ __launch_bounds__(256) void kan_silu_pack() {
    extern __shared__ __half sm[];           // [54][PK_STRIDE]
    const int tid = threadIdx.x;
    const int by  = blockIdx.x;              // 0..431
    const int b   = by / HOUT;
    const int y   = by - b * HOUT;
    const int base  = b * (CIN_ * HIN * HIN) + y * HIN;
    const int nbase = b * PIX_B + y * HOUT;

    const int q  = tid >> 6;                 // 0..3 (feature-lane group)
    const int xx = tid & 63;                 // 0..63; only xx<54 active
    if (xx < HOUT) {
        for (int i = q; i < NIF; i += 4)
            sm[xx * PK_STRIDE + i] = g_Fsilu[__ldg(g_kmap2 + i) + base + xx];
    }
    __syncthreads();
    for (int j = tid; j < HOUT * (NIF / 8); j += 256) {
        int r = j / (NIF / 8);
        int c = j - r * (NIF / 8);
        *(uint4*)(g_As + (nbase + r) * NIF + c * 8) =
            *(const uint4*)(sm + r * PK_STRIDE + c * 8);
    }
}

// ================= stage 2: weights + tap map =================
__global__ __launch_bounds__(256) void kan_wprep(const float* __restrict__ bw,
                                                 const float* __restrict__ sw,
                                                 const float* __restrict__ sc) {
    int idx = blockIdx.x * blockDim.x + threadIdx.x;
    if (idx < NIF) {
        int c  = idx / 9;
        int kk = idx - c * 9;
        int ky = kk / 3;
        int kx = kk - ky * 3;
        g_kmap2[idx] = c * (HIN * HIN) + ky * HIN + kx;
    }
    if (idx >= COUT_ * NIF) return;
    int o = idx & (COUT_ - 1);
    int i = idx >> 7;                        // 0..575 (= c*9+kk)
    float scale = sc[o * NIF + i];
    __half* dst = g_W2h + o * KTOT + i * 8;  // spline block: k = i*8 + f
#pragma unroll
    for (int g = 0; g < 8; ++g)
        dst[g] = __float2half_rn(sw[(o * NIF + i) * 8 + g] * scale);
    g_W2h[o * KTOT + KSPL + i] = __float2half_rn(bw[o * NIF + i]);   // silu block
}

// ================= stage 3: warp-specialized fp16 mma GEMM =================
// 4 consumer warps (wid 0-3): warp tile 48x64, 2m x 2n grid. 2 producer warps.
__global__ __launch_bounds__(THREADS, 2) void kan_mma(float* __restrict__ out) {
    extern __shared__ char dsm_raw[];
    __shared__ int sh_roff[MTILE];
    __shared__ int sh_ooff[MTILE];
    __shared__ alignas(8) unsigned long long sh_mbar[2 * NBUF];  // full[0..2], empty[0..2]

    const uint32_t sb0 = smem_u32(dsm_raw);
    const uint32_t smb = (sb0 + 255) & ~255u;
    char* const dsm = dsm_raw + (smb - sb0);

    const int tid  = threadIdx.x;
    const int wid  = tid >> 5;
    const int lane = tid & 31;
    const int base_n = blockIdx.x * MTILE;

    const uint32_t mb_full  = smem_u32(&sh_mbar[0]);
    const uint32_t mb_empty = smem_u32(&sh_mbar[NBUF]);

    if (tid < MTILE) {
        int n   = base_n + tid;
        int b   = n / PIX_B;
        int rem = n - b * PIX_B;
        int y   = rem / HOUT;
        int xx  = rem - y * HOUT;
        sh_roff[tid] = b * (CIN_ * HIN * HIN) + y * HIN + xx;
        sh_ooff[tid] = b * (COUT_ * PIX_B) + rem;
    }
    if (tid == 0) {
#pragma unroll
        for (int b = 0; b < NBUF; ++b) {
            MBAR_INIT(mb_full  + b * 8, 64);   // cp.async completion from 64 producer threads
            MBAR_INIT(mb_empty + b * 8, 128);  // 128 consumer threads
        }
    }
    __syncthreads();

    if (wid >= 4) {
        // ================== PRODUCERS (warps 4-5, 64 threads) ==================
        const int p  = tid - 128;
        const int hi = p >> 3;               // 0..7
        const int lo = p & 7;                // 0..7
        int buf = 0, ph = 1;                 // producer cursor: first empty-wait passes
        for (int s = 0; s < NSTG; ++s) {
            MBAR_WAIT(mb_empty + buf * 8, ph);
            const uint32_t Ab = smb + buf * STAGE_BYTES;
            const uint32_t Bb = Ab + A_STAGE_BYTES;
            if (s < NSPL_STG) {
                // A: 96 m x 8 f-groups of 16B. g=hi fixed, m=lo+8t.
                const int km = __ldg(g_kmap2 + s * 8 + hi);
#pragma unroll
                for (int t = 0; t < 12; ++t) {
                    int m = lo + 8 * t;
                    CP16(Ab + (uint32_t)(m * SAK + hi * 8) * 2,
                         (const char*)(g_Fs + km + sh_roff[m]));
                }
            } else {
                // A silu: 96 m x 8 chunks of 16B from prepacked g_As rows.
                const int k0 = (s - NSPL_STG) * KC;
#pragma unroll
                for (int t = 0; t < 12; ++t) {
                    int m = lo + 8 * t;
                    CP16(Ab + (uint32_t)(m * SAK + hi * 8) * 2,
                         (const char*)(g_As + (base_n + m) * NIF + k0 + hi * 8));
                }
            }
            // B: 128 n x 8 chunks of 16B. c=lo, n=hi+8t.
            {
                const __half* wb = g_W2h + s * KC + lo * 8;
#pragma unroll
                for (int t = 0; t < 16; ++t) {
                    int n = hi + 8 * t;
                    CP16(Bb + (uint32_t)(n * SBH + lo * 8) * 2, wb + n * KTOT);
                }
            }
            CPARRIVE(mb_full + buf * 8);
            if (++buf == NBUF) { buf = 0; ph ^= 1; }
        }
        __syncthreads();   // match consumer epilogue barrier 1
        __syncthreads();   // match consumer epilogue barrier 2
        return;
    }

    // ================== CONSUMERS (warps 0-3, 48x64 tiles) ==================
    const int wm = wid & 1;                  // rows wm*48
    const int wn = wid >> 1;                 // cols wn*64
    const uint32_t a_lane = (uint32_t)(((lane & 7) + (((lane >> 3) & 1) << 3)) * SAK
                                       + ((lane >> 4) << 3)) * 2;
    const uint32_t b_lane = (uint32_t)(((lane & 7) + ((lane >> 4) << 3)) * SBH
                                       + (((lane >> 3) & 1) << 3)) * 2;

    float acc[3][8][4];
#pragma unroll
    for (int mt = 0; mt < 3; ++mt)
#pragma unroll
        for (int nt = 0; nt < 8; ++nt)
#pragma unroll
            for (int e = 0; e < 4; ++e) acc[mt][nt][e] = 0.0f;

    int buf = 0, ph = 0;                     // consumer cursor
    for (int s = 0; s < NSTG; ++s) {
        MBAR_WAIT(mb_full + buf * 8, ph);
        const uint32_t Ab = smb + buf * STAGE_BYTES;
        const uint32_t Bb = Ab + A_STAGE_BYTES;
#pragma unroll
        for (int ks = 0; ks < 4; ++ks) {
            const int k0 = ks * 16;
            uint32_t a[3][4], b[4][4];
#pragma unroll
            for (int mt = 0; mt < 3; ++mt)
                ldsm4(a[mt], Ab + a_lane
                      + (uint32_t)((wm * 48 + mt * 16) * SAK + k0) * 2);
#pragma unroll
            for (int q = 0; q < 4; ++q)
                ldsm4(b[q], Bb + b_lane
                      + (uint32_t)((wn * 64 + q * 16) * SBH + k0) * 2);
#pragma unroll
            for (int mt = 0; mt < 3; ++mt)
#pragma unroll
                for (int nt = 0; nt < 8; ++nt)
                    mma16(acc[mt][nt], a[mt], &b[nt >> 1][(nt & 1) * 2]);
        }
        MBAR_ARRIVE(mb_empty + buf * 8);
        if (++buf == NBUF) { buf = 0; ph ^= 1; }
    }

    __syncthreads();   // all buffers consumed -> reuse as sout

    // epilogue: regs -> smem transpose -> coalesced strided stores
    float* sout = (float*)dsm;
    const int g  = lane >> 2;
    const int t2 = (lane & 3) * 2;
#pragma unroll
    for (int mt = 0; mt < 3; ++mt) {
        int r = wm * 48 + mt * 16 + g;
#pragma unroll
        for (int nt = 0; nt < 8; ++nt) {
            int cc = wn * 64 + nt * 8 + t2;
            sout[r * SO + cc]           = acc[mt][nt][0];
            sout[r * SO + cc + 1]       = acc[mt][nt][1];
            sout[(r + 8) * SO + cc]     = acc[mt][nt][2];
            sout[(r + 8) * SO + cc + 1] = acc[mt][nt][3];
        }
    }
    __syncthreads();
#pragma unroll
    for (int o = wid; o < COUT_; o += 4) {
#pragma unroll
        for (int rg = 0; rg < 3; ++rg) {
            int r = rg * 32 + lane;
            out[sh_ooff[r] + o * PIX_B] = sout[r * SO + o];
        }
    }
}

// ================= launch =================
extern "C" void kernel_launch(void* const* d_in, const int* in_sizes, int n_in,
                              void* d_out, int out_size) {
    const float* x  = (const float*)d_in[0];   // (8,64,56,56)
    const float* bw = (const float*)d_in[1];   // (128,576)
    const float* sw = (const float*)d_in[2];   // (128,576,8)
    const float* sc = (const float*)d_in[3];   // (128,576)
    float* out = (float*)d_out;                // (8,128,54,54)
    (void)in_sizes; (void)n_in; (void)out_size;

    cudaFuncSetAttribute(kan_mma, cudaFuncAttributeMaxDynamicSharedMemorySize, DYN_SMEM);
    cudaFuncSetAttribute(kan_silu_pack, cudaFuncAttributeMaxDynamicSharedMemorySize, PK_SMEM);

    kan_wprep<<<(COUT_ * NIF + 255) / 256, 256>>>(bw, sw, sc);   // builds g_kmap2 first
    kan_feat<<<(NPIX_TOT / 2 + 255) / 256, 256>>>(x);
    kan_silu_pack<<<BATCH * HOUT, 256, PK_SMEM>>>();
    kan_mma<<<CTAS, THREADS, DYN_SMEM>>>(out);
}